// round 3
// baseline (speedup 1.0000x reference)
#include <cuda_runtime.h>

// Problem constants
#define BATCH 512
#define TLEN  256
#define HID   512
#define G4    2048   // 4*HID
#define HALF  256
#define TGT   28

// GEMM tiling
#define BM 64
#define BN 64
#define BK 16
#define NTHREADS 256
#define MTILES (BATCH / BM)   // 8
#define NTILES (G4 / BN)      // 32
#define NCTAS  (MTILES * NTILES) // 256
#define PAD 4
#define SMSTR (BM + PAD)      // 68 floats per smem row (272B, 16B-aligned)

// ---------------- device scratch (no allocations allowed) ----------------
__device__ __align__(16) float g_h[2][BATCH * HID];   // double-buffered hidden state
__device__ __align__(16) float g_Wp[G4 * HID];        // W_hh reordered: row r = k*4 + gate
__device__ __align__(16) float g_wihp[G4];            // W_ih reordered
__device__ __align__(16) float g_biasp[G4];           // (b_ih + b_hh) reordered
__device__ __align__(16) float g_hid[BATCH * HALF];   // fc1 output
__device__ unsigned int g_barcnt;                     // zero-initialized
__device__ volatile unsigned int g_bargen;

// ---------------- grid-wide barrier (sense-reversing) ----------------
__device__ __forceinline__ void gridbar() {
    __threadfence();      // make this thread's global writes visible
    __syncthreads();      // CTA-level: everyone's writes ordered before tid0 proceeds
    if (threadIdx.x == 0) {
        unsigned int gen = g_bargen;           // snapshot BEFORE arriving
        if (atomicAdd(&g_barcnt, 1u) == NCTAS - 1u) {
            g_barcnt = 0u;
            __threadfence();
            g_bargen = gen + 1u;               // release
        } else {
            while (g_bargen == gen) { }        // spin (volatile -> L2 reads)
            __threadfence();                   // acquire
        }
    }
    __syncthreads();
}

__device__ __forceinline__ float sigmoidf(float x) {
    return 1.0f / (1.0f + __expf(-x));
}

__global__ __launch_bounds__(NTHREADS, 2)
void lstm_persistent_kernel(
    const float* __restrict__ seq,    // [B, T, 1]
    const float* __restrict__ W_ih,   // [4H, 1]
    const float* __restrict__ W_hh,   // [4H, H]
    const float* __restrict__ b_ih,   // [4H]
    const float* __restrict__ b_hh,   // [4H]
    const float* __restrict__ fc1w,   // [HALF, H]
    const float* __restrict__ fc1b,   // [HALF]
    const float* __restrict__ fc2w,   // [TGT, HALF]
    const float* __restrict__ fc2b,   // [TGT]
    float* __restrict__ out)          // [B, TGT, 1]
{
    __shared__ __align__(16) float As[2][BK][SMSTR];
    __shared__ __align__(16) float Bs[2][BK][SMSTR];
    __shared__ __align__(16) float hs[2][HID];   // for fc1 tail

    const int tid = threadIdx.x;
    const int cta = blockIdx.x;
    const int gid = cta * NTHREADS + tid;
    const int gsz = NCTAS * NTHREADS;            // 65536

    // ---------------- prep: reorder weights, zero state ----------------
    // Wp[(k*4+g)*H + j] = W_hh[(g*512 + k)*H + j]
    for (int e = gid; e < G4 * HID; e += gsz) {
        int r = e >> 9;          // row (0..2047)
        int j = e & 511;         // col
        int k = r >> 2;
        int q = r & 3;
        g_Wp[e] = W_hh[((q << 9) + k) * HID + j];
    }
    for (int e = gid; e < G4; e += gsz) {
        int k = e >> 2, q = e & 3;
        int src = (q << 9) + k;
        g_wihp[e] = W_ih[src];
        g_biasp[e] = b_ih[src] + b_hh[src];
    }
    for (int e = gid; e < BATCH * HID; e += gsz) {
        g_h[0][e] = 0.0f;
    }
    gridbar();

    // ---------------- per-CTA tile geometry ----------------
    const int tileM = cta / NTILES;
    const int tileN = cta % NTILES;
    const int b0 = tileM * BM;
    const int n0 = tileN * BN;

    const int tidm = tid & 15;          // 0..15 (batch dim)
    const int tidn = tid >> 4;          // 0..15 (gate-row dim)
    const int m0 = 2 * tidm;            // m-fragment: {m0, m0+1, m1, m1+1}
    const int m1 = 32 + 2 * tidm;
    const int nb = n0 + tidn * 4;       // 4 consecutive reordered rows = gates of unit:
    const int kunit = nb >> 2;          // hidden unit owned by this thread

    const int ms[4] = { m0, m0 + 1, m1, m1 + 1 };
    int hoff[4], soff[4];
    #pragma unroll
    for (int i = 0; i < 4; i++) {
        hoff[i] = (b0 + ms[i]) * HID + kunit;
        soff[i] = (b0 + ms[i]) * TLEN;
    }

    // loader mapping: 256 threads load 64 rows x 16 cols as float4
    const int lrow = tid >> 2;          // 0..63
    const int lcol = (tid & 3) << 2;    // 0,4,8,12

    const float4 wih4  = *(const float4*)&g_wihp[nb];
    const float4 bias4 = *(const float4*)&g_biasp[nb];

    float creg[4] = {0.f, 0.f, 0.f, 0.f};   // cell state lives in registers all T steps

    // ---------------- recurrent loop ----------------
    for (int t = 0; t < TLEN; ++t) {
        const float* hin = g_h[t & 1];
        float* hout = g_h[(t & 1) ^ 1];

        float acc[4][4];
        #pragma unroll
        for (int i = 0; i < 4; i++)
            #pragma unroll
            for (int j = 0; j < 4; j++) acc[i][j] = 0.0f;

        // prologue: chunk 0 -> smem buf 0
        {
            float4 av = *(const float4*)&hin[(b0 + lrow) * HID + lcol];
            float4 bv = *(const float4*)&g_Wp[(n0 + lrow) * HID + lcol];
            As[0][lcol + 0][lrow] = av.x; As[0][lcol + 1][lrow] = av.y;
            As[0][lcol + 2][lrow] = av.z; As[0][lcol + 3][lrow] = av.w;
            Bs[0][lcol + 0][lrow] = bv.x; Bs[0][lcol + 1][lrow] = bv.y;
            Bs[0][lcol + 2][lrow] = bv.z; Bs[0][lcol + 3][lrow] = bv.w;
        }
        __syncthreads();

        int cur = 0;
        #pragma unroll 1
        for (int kt = 0; kt < HID / BK; ++kt) {
            float4 av2, bv2;
            const bool more = (kt + 1 < HID / BK);
            if (more) {
                int kk = (kt + 1) * BK;
                av2 = *(const float4*)&hin[(b0 + lrow) * HID + kk + lcol];
                bv2 = *(const float4*)&g_Wp[(n0 + lrow) * HID + kk + lcol];
            }
            // compute on current buffer
            #pragma unroll
            for (int k = 0; k < BK; ++k) {
                float2 a01 = *(const float2*)&As[cur][k][m0];
                float2 a23 = *(const float2*)&As[cur][k][m1];
                float4 b4  = *(const float4*)&Bs[cur][k][tidn * 4];
                float am[4] = { a01.x, a01.y, a23.x, a23.y };
                float bn[4] = { b4.x, b4.y, b4.z, b4.w };
                #pragma unroll
                for (int i = 0; i < 4; i++)
                    #pragma unroll
                    for (int j = 0; j < 4; j++)
                        acc[i][j] += am[i] * bn[j];
            }
            if (more) {
                int nxt = cur ^ 1;
                As[nxt][lcol + 0][lrow] = av2.x; As[nxt][lcol + 1][lrow] = av2.y;
                As[nxt][lcol + 2][lrow] = av2.z; As[nxt][lcol + 3][lrow] = av2.w;
                Bs[nxt][lcol + 0][lrow] = bv2.x; Bs[nxt][lcol + 1][lrow] = bv2.y;
                Bs[nxt][lcol + 2][lrow] = bv2.z; Bs[nxt][lcol + 3][lrow] = bv2.w;
            }
            __syncthreads();
            cur ^= 1;
        }

        // epilogue: gates -> activations -> c,h update (gate order i,f,g,o)
        #pragma unroll
        for (int i = 0; i < 4; i++) {
            float xv = seq[soff[i] + t];
            float gi = acc[i][0] + xv * wih4.x + bias4.x;
            float gf = acc[i][1] + xv * wih4.y + bias4.y;
            float gg = acc[i][2] + xv * wih4.z + bias4.z;
            float go = acc[i][3] + xv * wih4.w + bias4.w;
            float I = sigmoidf(gi);
            float F = sigmoidf(gf);
            float G = tanhf(gg);
            float O = sigmoidf(go);
            float cc = F * creg[i] + I * G;
            creg[i] = cc;
            hout[hoff[i]] = O * tanhf(cc);
        }

        gridbar();
    }

    // ---------------- fc1: hid = relu(h @ fc1w^T + fc1b) ----------------
    {
        const float* hfin = g_h[TLEN & 1];   // final h is in buffer 0
        int bb = cta * 2;                    // 256 CTAs x 2 batch rows = 512
        for (int e = tid; e < 2 * HID; e += NTHREADS)
            hs[e >> 9][e & 511] = hfin[(bb + (e >> 9)) * HID + (e & 511)];
        __syncthreads();

        int n = tid;                         // HALF == NTHREADS == 256
        const float* wr = fc1w + n * HID;
        float s0 = fc1b[n], s1 = s0;
        #pragma unroll 8
        for (int k = 0; k < HID; ++k) {
            float w = wr[k];
            s0 += hs[0][k] * w;
            s1 += hs[1][k] * w;
        }
        g_hid[bb * HALF + n]       = fmaxf(s0, 0.0f);
        g_hid[(bb + 1) * HALF + n] = fmaxf(s1, 0.0f);
    }
    gridbar();

    // ---------------- fc2: out = hid @ fc2w^T + fc2b ----------------
    for (int o = gid; o < BATCH * TGT; o += gsz) {
        int b = o / TGT;
        int tt = o - b * TGT;
        const float* hr = g_hid + b * HALF;
        const float* wr = fc2w + tt * HALF;
        float s = fc2b[tt];
        #pragma unroll 8
        for (int k = 0; k < HALF; ++k) s += hr[k] * wr[k];
        out[o] = s;
    }
}

extern "C" void kernel_launch(void* const* d_in, const int* in_sizes, int n_in,
                              void* d_out, int out_size) {
    (void)in_sizes; (void)n_in; (void)out_size;
    lstm_persistent_kernel<<<NCTAS, NTHREADS>>>(
        (const float*)d_in[0],  // sequence
        (const float*)d_in[1],  // W_ih
        (const float*)d_in[2],  // W_hh
        (const float*)d_in[3],  // b_ih
        (const float*)d_in[4],  // b_hh
        (const float*)d_in[5],  // fc1_w
        (const float*)d_in[6],  // fc1_b
        (const float*)d_in[7],  // fc2_w
        (const float*)d_in[8],  // fc2_b
        (float*)d_out);
}